// round 9
// baseline (speedup 1.0000x reference)
#include <cuda_runtime.h>
#include <cuda_fp16.h>
#include <cstdint>

// ---------------- problem dims ----------------
#define T_DIM 8192
#define D_DIM 1024
#define H_DIM 4096

// scratch (device globals: no allocation allowed)
__device__ __half g_h  [(size_t)T_DIM * H_DIM];   // 64 MB intermediate (fp16)
__device__ __half g_xh [(size_t)T_DIM * D_DIM];   // fp16 x
__device__ __half g_wfc[(size_t)H_DIM * D_DIM];   // fp16 W_fc
__device__ __half g_wpr[(size_t)D_DIM * H_DIM];   // fp16 W_proj

// ---------------- helpers ----------------
__device__ __forceinline__ uint32_t smem_u32(const void* p) {
    uint32_t a;
    asm("{ .reg .u64 t; cvta.to.shared.u64 t, %1; cvt.u32.u64 %0, t; }" : "=r"(a) : "l"(p));
    return a;
}
__device__ __forceinline__ uint32_t swz(uint32_t b) {   // SW128: XOR bits[6:4] with bits[9:7]
    return b ^ ((b >> 3) & 0x70u);
}
__device__ __forceinline__ void cp_async16(uint32_t saddr, const void* g) {
    asm volatile("cp.async.cg.shared.global [%0], [%1], 16;" :: "r"(saddr), "l"(g));
}
#define CP_COMMIT() asm volatile("cp.async.commit_group;" ::: "memory")
#define CP_WAIT1()  asm volatile("cp.async.wait_group 1;" ::: "memory")

#define LDSM_X4(r0, r1, r2, r3, addr) \
    asm volatile("ldmatrix.sync.aligned.m8n8.x4.shared.b16 {%0,%1,%2,%3}, [%4];" \
        : "=r"(r0), "=r"(r1), "=r"(r2), "=r"(r3) : "r"(addr))

// fp16 MMA, fp32 accumulate: D(16x8) += A(16x16) * B(16x8)
#define MMA_F16(c0, c1, c2, c3, a0, a1, a2, a3, b0, b1) \
    asm volatile("mma.sync.aligned.m16n8k16.row.col.f32.f16.f16.f32 " \
        "{%0,%1,%2,%3}, {%4,%5,%6,%7}, {%8,%9}, {%0,%1,%2,%3};" \
        : "+f"(c0), "+f"(c1), "+f"(c2), "+f"(c3) \
        : "r"(a0), "r"(a1), "r"(a2), "r"(a3), "r"(b0), "r"(b1))

// ---------------- GEMM config ----------------
static constexpr int BLK_M = 128;
static constexpr int BLK_N = 128;
static constexpr int BLK_K = 64;                 // fp16 elems -> 128 bytes per row
static constexpr int STAGES = 3;                 // 96KB -> 2 CTAs / SM
static constexpr int A_BYTES = BLK_M * BLK_K * 2;          // 16384
static constexpr int B_BYTES = BLK_N * BLK_K * 2;          // 16384
static constexpr int STAGE_BYTES = A_BYTES + B_BYTES;      // 32768
static constexpr int SMEM_TOTAL = STAGES * STAGE_BYTES;    // 98304

// load one 128x64 A tile + 128x64 B tile (fp16) into stage at sBase
__device__ __forceinline__ void load_tile(uint32_t sBase, const __half* __restrict__ gA,
                                          const __half* __restrict__ gB, int K, int kt, int tid)
{
    const int k0 = kt * BLK_K;
    #pragma unroll
    for (int i = 0; i < 4; ++i) {                  // A: 1024 x 16B chunks / 256 thr
        int chunk = tid + i * 256;
        int row = chunk >> 3, unit = chunk & 7;    // 8 x 16B units per 128B row
        uint32_t off = row * 128 + unit * 16;
        cp_async16(sBase + swz(off), gA + (size_t)row * K + k0 + unit * 8);
    }
    #pragma unroll
    for (int i = 0; i < 4; ++i) {                  // B
        int chunk = tid + i * 256;
        int row = chunk >> 3, unit = chunk & 7;
        uint32_t off = row * 128 + unit * 16;
        cp_async16(sBase + A_BYTES + swz(off), gB + (size_t)row * K + k0 + unit * 8);
    }
}

// OUT16: write C as fp16 (GEMM1 -> h). Otherwise fp32.
template <bool RELU2, bool OUT16>
__global__ void __launch_bounds__(256, 2) gemm_f16_mma(
    const __half* __restrict__ A,   // [M, K] row-major (K contiguous)
    const __half* __restrict__ B,   // [N, K] row-major (K contiguous)
    void* __restrict__ Cv,          // [M, N]
    int K, int ldc)
{
    extern __shared__ char smem[];
    const uint32_t sb = smem_u32(smem);
    const int tid  = threadIdx.x;
    const int lane = tid & 31;
    const int warp = tid >> 5;
    const int wm = (warp & 3) * 32;        // warp grid 4x2, warp tile 32x64
    const int wn = (warp >> 2) * 64;
    // s-step stagger: odd warps walk k-steps 2,3,0,1 -> desynchronizes LDSM bursts
    const uint32_t sOff = (warp & 1) << 1;

    const __half* gA = A + (size_t)blockIdx.x * BLK_M * K;
    const __half* gB = B + (size_t)blockIdx.y * BLK_N * K;
    const int KT = K / BLK_K;

    // prologue: 2 stages in flight
    load_tile(sb, gA, gB, K, 0, tid);
    CP_COMMIT();
    load_tile(sb + STAGE_BYTES, gA, gB, K, 1, tid);
    CP_COMMIT();

    // ldmatrix linear offsets (swizzle XOR applied per access)
    const uint32_t xmask = (uint32_t)(lane & 7) << 4;
    const uint32_t aLin0 = (uint32_t)(wm + (lane & 15)) * 128 + (uint32_t)(lane >> 4) * 16;
    const uint32_t aLin1 = aLin0 + 16 * 128;
    uint32_t bLin[4];
    #pragma unroll
    for (int jp = 0; jp < 4; ++jp)
        bLin[jp] = (uint32_t)(wn + jp * 16 + (lane & 15)) * 128 + (uint32_t)(lane >> 4) * 16;

    float c[2][8][4];
    #pragma unroll
    for (int mi = 0; mi < 2; ++mi)
        #pragma unroll
        for (int j = 0; j < 8; ++j)
            #pragma unroll
            for (int q = 0; q < 4; ++q) c[mi][j][q] = 0.0f;

    int curSt = 0, pfSt = 2;
    for (int kt = 0; kt < KT; ++kt) {
        CP_WAIT1();
        __syncthreads();

        // prefetch k-tile kt+2 into the slot consumed at kt-1
        int nk = kt + 2;
        if (nk < KT) load_tile(sb + pfSt * STAGE_BYTES, gA, gB, K, nk, tid);
        CP_COMMIT();
        if (++pfSt == STAGES) pfSt = 0;

        const uint32_t st = sb + curSt * STAGE_BYTES;
        if (++curSt == STAGES) curSt = 0;

        #pragma unroll
        for (int s = 0; s < 4; ++s) {              // 4 x K=16 steps (32B each)
            const uint32_t add = ((s + sOff) & 3) * 32;   // warp-parity staggered order
            uint32_t a[2][4], b[4][4];
            LDSM_X4(a[0][0], a[0][1], a[0][2], a[0][3], st + ((aLin0 + add) ^ xmask));
            LDSM_X4(a[1][0], a[1][1], a[1][2], a[1][3], st + ((aLin1 + add) ^ xmask));
            #pragma unroll
            for (int jp = 0; jp < 4; ++jp)
                LDSM_X4(b[jp][0], b[jp][1], b[jp][2], b[jp][3],
                        st + A_BYTES + ((bLin[jp] + add) ^ xmask));
            #pragma unroll
            for (int mi = 0; mi < 2; ++mi)
                #pragma unroll
                for (int jp = 0; jp < 4; ++jp) {
                    MMA_F16(c[mi][2 * jp][0], c[mi][2 * jp][1], c[mi][2 * jp][2], c[mi][2 * jp][3],
                            a[mi][0], a[mi][1], a[mi][2], a[mi][3], b[jp][0], b[jp][2]);
                    MMA_F16(c[mi][2 * jp + 1][0], c[mi][2 * jp + 1][1], c[mi][2 * jp + 1][2], c[mi][2 * jp + 1][3],
                            a[mi][0], a[mi][1], a[mi][2], a[mi][3], b[jp][1], b[jp][3]);
                }
        }
    }

    // epilogue
    const int row0 = blockIdx.x * BLK_M + wm + (lane >> 2);
    const int col0 = blockIdx.y * BLK_N + wn + (lane & 3) * 2;
    #pragma unroll
    for (int mi = 0; mi < 2; ++mi)
        #pragma unroll
        for (int rr = 0; rr < 2; ++rr) {
            const int row = row0 + mi * 16 + rr * 8;
            #pragma unroll
            for (int j = 0; j < 8; ++j) {
                float v0 = c[mi][j][rr * 2], v1 = c[mi][j][rr * 2 + 1];
                if (RELU2) {
                    v0 = fmaxf(v0, 0.0f); v0 *= v0;
                    v1 = fmaxf(v1, 0.0f); v1 *= v1;
                }
                if (OUT16) {
                    __half* base = (__half*)Cv + (size_t)row * ldc + col0;
                    __half2 hv = __floats2half2_rn(v0, v1);
                    *reinterpret_cast<__half2*>(base + j * 8) = hv;
                } else {
                    float* base = (float*)Cv + (size_t)row * ldc + col0;
                    *reinterpret_cast<float2*>(base + j * 8) = make_float2(v0, v1);
                }
            }
        }
}

// ---------------- fused fp32 -> fp16 RN pre-pass (all three tensors) ----------------
__global__ void to_half_all_kernel(const float4* __restrict__ x,   __half2* __restrict__ xo,
                                   const float4* __restrict__ wf,  __half2* __restrict__ wfo,
                                   const float4* __restrict__ wp,  __half2* __restrict__ wpo)
{
    const int n4x = T_DIM * D_DIM / 4;
    const int n4f = H_DIM * D_DIM / 4;
    const int n4p = D_DIM * H_DIM / 4;
    const int stride = gridDim.x * blockDim.x;
    for (int i = blockIdx.x * blockDim.x + threadIdx.x; i < n4x + n4f + n4p; i += stride) {
        const float4* src; __half2* dst; int j;
        if (i < n4x)            { src = x;  dst = xo;  j = i; }
        else if (i < n4x + n4f) { src = wf; dst = wfo; j = i - n4x; }
        else                    { src = wp; dst = wpo; j = i - n4x - n4f; }
        float4 v = src[j];
        dst[2 * j]     = __floats2half2_rn(v.x, v.y);
        dst[2 * j + 1] = __floats2half2_rn(v.z, v.w);
    }
}

// ---------------- host side ----------------
extern "C" void kernel_launch(void* const* d_in, const int* in_sizes, int n_in,
                              void* d_out, int out_size)
{
    const float* x   = (const float*)d_in[0];  // [8192, 1024]
    const float* wfc = (const float*)d_in[1];  // [4096, 1024]
    const float* wpr = (const float*)d_in[2];  // [1024, 4096]
    float* out = (float*)d_out;                // [8192, 1024]

    __half *h, *xh, *wfch, *wprh;
    cudaGetSymbolAddress((void**)&h,    g_h);
    cudaGetSymbolAddress((void**)&xh,   g_xh);
    cudaGetSymbolAddress((void**)&wfch, g_wfc);
    cudaGetSymbolAddress((void**)&wprh, g_wpr);

    cudaFuncSetAttribute(gemm_f16_mma<true, true>,
                         cudaFuncAttributeMaxDynamicSharedMemorySize, SMEM_TOTAL);
    cudaFuncSetAttribute(gemm_f16_mma<false, false>,
                         cudaFuncAttributeMaxDynamicSharedMemorySize, SMEM_TOTAL);

    // fp32 -> fp16 (RN) pre-pass; fp16 mantissa == tf32 mantissa (11 bits effective)
    to_half_all_kernel<<<2368, 256>>>((const float4*)x,   (__half2*)xh,
                                      (const float4*)wfc, (__half2*)wfch,
                                      (const float4*)wpr, (__half2*)wprh);

    // GEMM1: h = relu(x @ Wfc^T)^2   [8192, 4096], K = 1024, out fp16
    gemm_f16_mma<true, true><<<dim3(T_DIM / BLK_M, H_DIM / BLK_N), 256, SMEM_TOTAL>>>(
        xh, wfch, h, D_DIM, H_DIM);

    // GEMM2: out = h @ Wpr^T         [8192, 1024], K = 4096, out fp32
    gemm_f16_mma<false, false><<<dim3(T_DIM / BLK_M, D_DIM / BLK_N), 256, SMEM_TOTAL>>>(
        h, wprh, out, H_DIM, D_DIM);
}

// round 10
// speedup vs baseline: 1.5266x; 1.5266x over previous
#include <cuda_runtime.h>
#include <cuda_fp16.h>
#include <cstdint>

// ---------------- problem dims ----------------
#define T_DIM 8192
#define D_DIM 1024
#define H_DIM 4096

// scratch (device globals: no allocation allowed)
__device__ __half g_h  [(size_t)T_DIM * H_DIM];   // 64 MB intermediate (fp16)
__device__ __half g_xh [(size_t)T_DIM * D_DIM];   // fp16 x
__device__ __half g_wfc[(size_t)H_DIM * D_DIM];   // fp16 W_fc
__device__ __half g_wpr[(size_t)D_DIM * H_DIM];   // fp16 W_proj

// ---------------- helpers ----------------
__device__ __forceinline__ uint32_t smem_u32(const void* p) {
    uint32_t a;
    asm("{ .reg .u64 t; cvta.to.shared.u64 t, %1; cvt.u32.u64 %0, t; }" : "=r"(a) : "l"(p));
    return a;
}
__device__ __forceinline__ uint32_t swz(uint32_t b) {   // SW128: XOR bits[6:4] with bits[9:7]
    return b ^ ((b >> 3) & 0x70u);
}
__device__ __forceinline__ void cp_async16(uint32_t saddr, const void* g) {
    asm volatile("cp.async.cg.shared.global [%0], [%1], 16;" :: "r"(saddr), "l"(g));
}
#define CP_COMMIT() asm volatile("cp.async.commit_group;" ::: "memory")
#define CP_WAIT1()  asm volatile("cp.async.wait_group 1;" ::: "memory")

#define LDSM_X4(r0, r1, r2, r3, addr) \
    asm volatile("ldmatrix.sync.aligned.m8n8.x4.shared.b16 {%0,%1,%2,%3}, [%4];" \
        : "=r"(r0), "=r"(r1), "=r"(r2), "=r"(r3) : "r"(addr))

// fp16 MMA, fp32 accumulate: D(16x8) += A(16x16) * B(16x8)
#define MMA_F16(c0, c1, c2, c3, a0, a1, a2, a3, b0, b1) \
    asm volatile("mma.sync.aligned.m16n8k16.row.col.f32.f16.f16.f32 " \
        "{%0,%1,%2,%3}, {%4,%5,%6,%7}, {%8,%9}, {%0,%1,%2,%3};" \
        : "+f"(c0), "+f"(c1), "+f"(c2), "+f"(c3) \
        : "r"(a0), "r"(a1), "r"(a2), "r"(a3), "r"(b0), "r"(b1))

// ---------------- GEMM config ----------------
static constexpr int BLK_M = 128;
static constexpr int BLK_N = 128;
static constexpr int BLK_K = 64;                 // fp16 elems -> 128 bytes per row
static constexpr int STAGES = 3;                 // 96KB -> 2 CTAs / SM
static constexpr int A_BYTES = BLK_M * BLK_K * 2;          // 16384
static constexpr int B_BYTES = BLK_N * BLK_K * 2;          // 16384
static constexpr int STAGE_BYTES = A_BYTES + B_BYTES;      // 32768
static constexpr int SMEM_TOTAL = STAGES * STAGE_BYTES;    // 98304

// load one 128x64 A tile + 128x64 B tile (fp16) into stage at sBase
__device__ __forceinline__ void load_tile(uint32_t sBase, const __half* __restrict__ gA,
                                          const __half* __restrict__ gB, int K, int kt, int tid)
{
    const int k0 = kt * BLK_K;
    #pragma unroll
    for (int i = 0; i < 4; ++i) {                  // A: 1024 x 16B chunks / 256 thr
        int chunk = tid + i * 256;
        int row = chunk >> 3, unit = chunk & 7;    // 8 x 16B units per 128B row
        uint32_t off = row * 128 + unit * 16;
        cp_async16(sBase + swz(off), gA + (size_t)row * K + k0 + unit * 8);
    }
    #pragma unroll
    for (int i = 0; i < 4; ++i) {                  // B
        int chunk = tid + i * 256;
        int row = chunk >> 3, unit = chunk & 7;
        uint32_t off = row * 128 + unit * 16;
        cp_async16(sBase + A_BYTES + swz(off), gB + (size_t)row * K + k0 + unit * 8);
    }
}

// OUT16: write C as fp16 (GEMM1 -> h). Otherwise fp32.
template <bool RELU2, bool OUT16>
__global__ void __launch_bounds__(256, 2) gemm_f16_mma(
    const __half* __restrict__ A,   // [M, K] row-major (K contiguous)
    const __half* __restrict__ B,   // [N, K] row-major (K contiguous)
    void* __restrict__ Cv,          // [M, N]
    int K, int ldc)
{
    extern __shared__ char smem[];
    const uint32_t sb = smem_u32(smem);
    const int tid  = threadIdx.x;
    const int lane = tid & 31;
    const int warp = tid >> 5;
    const int wm = (warp & 3) * 32;        // warp grid 4x2, warp tile 32x64
    const int wn = (warp >> 2) * 64;

    const __half* gA = A + (size_t)blockIdx.x * BLK_M * K;
    const __half* gB = B + (size_t)blockIdx.y * BLK_N * K;
    const int KT = K / BLK_K;

    // prologue: 2 stages in flight
    load_tile(sb, gA, gB, K, 0, tid);
    CP_COMMIT();
    load_tile(sb + STAGE_BYTES, gA, gB, K, 1, tid);
    CP_COMMIT();

    // ldmatrix linear offsets (swizzle XOR applied per access)
    const uint32_t xmask = (uint32_t)(lane & 7) << 4;
    const uint32_t aLin0 = (uint32_t)(wm + (lane & 15)) * 128 + (uint32_t)(lane >> 4) * 16;
    const uint32_t aLin1 = aLin0 + 16 * 128;
    uint32_t bLin[4];
    #pragma unroll
    for (int jp = 0; jp < 4; ++jp)
        bLin[jp] = (uint32_t)(wn + jp * 16 + (lane & 15)) * 128 + (uint32_t)(lane >> 4) * 16;

    float c[2][8][4];
    #pragma unroll
    for (int mi = 0; mi < 2; ++mi)
        #pragma unroll
        for (int j = 0; j < 8; ++j)
            #pragma unroll
            for (int q = 0; q < 4; ++q) c[mi][j][q] = 0.0f;

    int curSt = 0, pfSt = 2;
    for (int kt = 0; kt < KT; ++kt) {
        CP_WAIT1();
        __syncthreads();

        // prefetch k-tile kt+2 into the slot consumed at kt-1
        int nk = kt + 2;
        if (nk < KT) load_tile(sb + pfSt * STAGE_BYTES, gA, gB, K, nk, tid);
        CP_COMMIT();
        if (++pfSt == STAGES) pfSt = 0;

        const uint32_t st = sb + curSt * STAGE_BYTES;
        if (++curSt == STAGES) curSt = 0;

        #pragma unroll
        for (int s = 0; s < 4; ++s) {              // 4 x K=16 steps (32B each)
            const uint32_t add = s * 32;
            uint32_t a[2][4], b[4][4];
            LDSM_X4(a[0][0], a[0][1], a[0][2], a[0][3], st + ((aLin0 + add) ^ xmask));
            LDSM_X4(a[1][0], a[1][1], a[1][2], a[1][3], st + ((aLin1 + add) ^ xmask));
            #pragma unroll
            for (int jp = 0; jp < 4; ++jp)
                LDSM_X4(b[jp][0], b[jp][1], b[jp][2], b[jp][3],
                        st + A_BYTES + ((bLin[jp] + add) ^ xmask));
            #pragma unroll
            for (int mi = 0; mi < 2; ++mi)
                #pragma unroll
                for (int jp = 0; jp < 4; ++jp) {
                    MMA_F16(c[mi][2 * jp][0], c[mi][2 * jp][1], c[mi][2 * jp][2], c[mi][2 * jp][3],
                            a[mi][0], a[mi][1], a[mi][2], a[mi][3], b[jp][0], b[jp][2]);
                    MMA_F16(c[mi][2 * jp + 1][0], c[mi][2 * jp + 1][1], c[mi][2 * jp + 1][2], c[mi][2 * jp + 1][3],
                            a[mi][0], a[mi][1], a[mi][2], a[mi][3], b[jp][1], b[jp][3]);
                }
        }
    }

    // epilogue
    const int row0 = blockIdx.x * BLK_M + wm + (lane >> 2);
    const int col0 = blockIdx.y * BLK_N + wn + (lane & 3) * 2;
    #pragma unroll
    for (int mi = 0; mi < 2; ++mi)
        #pragma unroll
        for (int rr = 0; rr < 2; ++rr) {
            const int row = row0 + mi * 16 + rr * 8;
            #pragma unroll
            for (int j = 0; j < 8; ++j) {
                float v0 = c[mi][j][rr * 2], v1 = c[mi][j][rr * 2 + 1];
                if (RELU2) {
                    v0 = fmaxf(v0, 0.0f); v0 *= v0;
                    v1 = fmaxf(v1, 0.0f); v1 *= v1;
                }
                if (OUT16) {
                    __half* base = (__half*)Cv + (size_t)row * ldc + col0;
                    __half2 hv = __floats2half2_rn(v0, v1);
                    *reinterpret_cast<__half2*>(base + j * 8) = hv;
                } else {
                    float* base = (float*)Cv + (size_t)row * ldc + col0;
                    *reinterpret_cast<float2*>(base + j * 8) = make_float2(v0, v1);
                }
            }
        }
}

// ---------------- fused fp32 -> fp16 RN pre-pass (all three tensors) ----------------
__global__ void to_half_all_kernel(const float4* __restrict__ x,   __half2* __restrict__ xo,
                                   const float4* __restrict__ wf,  __half2* __restrict__ wfo,
                                   const float4* __restrict__ wp,  __half2* __restrict__ wpo)
{
    const int n4x = T_DIM * D_DIM / 4;
    const int n4f = H_DIM * D_DIM / 4;
    const int n4p = D_DIM * H_DIM / 4;
    const int stride = gridDim.x * blockDim.x;
    for (int i = blockIdx.x * blockDim.x + threadIdx.x; i < n4x + n4f + n4p; i += stride) {
        const float4* src; __half2* dst; int j;
        if (i < n4x)            { src = x;  dst = xo;  j = i; }
        else if (i < n4x + n4f) { src = wf; dst = wfo; j = i - n4x; }
        else                    { src = wp; dst = wpo; j = i - n4x - n4f; }
        float4 v = src[j];
        dst[2 * j]     = __floats2half2_rn(v.x, v.y);
        dst[2 * j + 1] = __floats2half2_rn(v.z, v.w);
    }
}

// ---------------- host side ----------------
extern "C" void kernel_launch(void* const* d_in, const int* in_sizes, int n_in,
                              void* d_out, int out_size)
{
    const float* x   = (const float*)d_in[0];  // [8192, 1024]
    const float* wfc = (const float*)d_in[1];  // [4096, 1024]
    const float* wpr = (const float*)d_in[2];  // [1024, 4096]
    float* out = (float*)d_out;                // [8192, 1024]

    __half *h, *xh, *wfch, *wprh;
    cudaGetSymbolAddress((void**)&h,    g_h);
    cudaGetSymbolAddress((void**)&xh,   g_xh);
    cudaGetSymbolAddress((void**)&wfch, g_wfc);
    cudaGetSymbolAddress((void**)&wprh, g_wpr);

    cudaFuncSetAttribute(gemm_f16_mma<true, true>,
                         cudaFuncAttributeMaxDynamicSharedMemorySize, SMEM_TOTAL);
    cudaFuncSetAttribute(gemm_f16_mma<false, false>,
                         cudaFuncAttributeMaxDynamicSharedMemorySize, SMEM_TOTAL);

    // fp32 -> fp16 (RN) pre-pass; fp16 mantissa == tf32 mantissa (11 bits effective)
    to_half_all_kernel<<<2368, 256>>>((const float4*)x,   (__half2*)xh,
                                      (const float4*)wfc, (__half2*)wfch,
                                      (const float4*)wpr, (__half2*)wprh);

    // GEMM1: h = relu(x @ Wfc^T)^2   [8192, 4096], K = 1024, out fp16
    gemm_f16_mma<true, true><<<dim3(T_DIM / BLK_M, H_DIM / BLK_N), 256, SMEM_TOTAL>>>(
        xh, wfch, h, D_DIM, H_DIM);

    // GEMM2: out = h @ Wpr^T         [8192, 1024], K = 4096, out fp32
    gemm_f16_mma<false, false><<<dim3(T_DIM / BLK_M, D_DIM / BLK_N), 256, SMEM_TOTAL>>>(
        h, wprh, out, H_DIM, D_DIM);
}

// round 11
// speedup vs baseline: 1.5581x; 1.0206x over previous
#include <cuda_runtime.h>
#include <cuda_fp16.h>
#include <cstdint>

// ---------------- problem dims ----------------
#define T_DIM 8192
#define D_DIM 1024
#define H_DIM 4096

// scratch (device globals: no allocation allowed)
__device__ __half g_h  [(size_t)T_DIM * H_DIM];   // 64 MB intermediate (fp16)
__device__ __half g_xh [(size_t)T_DIM * D_DIM];   // fp16 x
__device__ __half g_wfc[(size_t)H_DIM * D_DIM];   // fp16 W_fc
__device__ __half g_wpr[(size_t)D_DIM * H_DIM];   // fp16 W_proj

// ---------------- helpers ----------------
__device__ __forceinline__ uint32_t smem_u32(const void* p) {
    uint32_t a;
    asm("{ .reg .u64 t; cvta.to.shared.u64 t, %1; cvt.u32.u64 %0, t; }" : "=r"(a) : "l"(p));
    return a;
}
__device__ __forceinline__ uint32_t swz(uint32_t b) {   // SW128: XOR bits[6:4] with bits[9:7]
    return b ^ ((b >> 3) & 0x70u);
}
__device__ __forceinline__ void cp_async16(uint32_t saddr, const void* g) {
    asm volatile("cp.async.cg.shared.global [%0], [%1], 16;" :: "r"(saddr), "l"(g));
}
#define CP_COMMIT() asm volatile("cp.async.commit_group;" ::: "memory")
#define CP_WAIT1()  asm volatile("cp.async.wait_group 1;" ::: "memory")

#define LDSM_X4(r0, r1, r2, r3, addr) \
    asm volatile("ldmatrix.sync.aligned.m8n8.x4.shared.b16 {%0,%1,%2,%3}, [%4];" \
        : "=r"(r0), "=r"(r1), "=r"(r2), "=r"(r3) : "r"(addr))

// fp16 MMA, fp32 accumulate: D(16x8) += A(16x16) * B(16x8)
#define MMA_F16(c0, c1, c2, c3, a0, a1, a2, a3, b0, b1) \
    asm volatile("mma.sync.aligned.m16n8k16.row.col.f32.f16.f16.f32 " \
        "{%0,%1,%2,%3}, {%4,%5,%6,%7}, {%8,%9}, {%0,%1,%2,%3};" \
        : "+f"(c0), "+f"(c1), "+f"(c2), "+f"(c3) \
        : "r"(a0), "r"(a1), "r"(a2), "r"(a3), "r"(b0), "r"(b1))

// ---------------- GEMM config ----------------
static constexpr int BLK_N = 128;
static constexpr int BLK_K = 64;                 // fp16 elems -> 128 bytes per row
static constexpr int STAGES = 3;                 // <=96KB -> 2 CTAs / SM
static constexpr int B_BYTES = BLK_N * BLK_K * 2;          // 16384
static constexpr int SMEM_TOTAL = STAGES * (128 * 128 + B_BYTES);   // 98304 (TM=128 worst case)

// GEMM2 mixed-tile split: 296 M128 tiles (rows 0-4735) + 432 M64 tiles (rows 4736-8191)
static constexpr int G2_BIG_TILES = 296;          // 37 tile-rows x 8 cols
static constexpr int G2_SMALL_ROW0 = 4736;        // 37 * 128

// load one TMx64 A tile + 128x64 B tile (fp16) into stage at sBase
template <int TM>
__device__ __forceinline__ void load_tile_t(uint32_t sBase, const __half* __restrict__ gA,
                                            const __half* __restrict__ gB, int K, int kt, int tid)
{
    const int k0 = kt * BLK_K;
    constexpr int A_BY = TM * 128;
    #pragma unroll
    for (int i = 0; i < TM * 8 / 256; ++i) {       // A: TM*8 x 16B chunks / 256 thr
        int chunk = tid + i * 256;
        int row = chunk >> 3, unit = chunk & 7;    // 8 x 16B units per 128B row
        uint32_t off = row * 128 + unit * 16;
        cp_async16(sBase + swz(off), gA + (size_t)row * K + k0 + unit * 8);
    }
    #pragma unroll
    for (int i = 0; i < 4; ++i) {                  // B
        int chunk = tid + i * 256;
        int row = chunk >> 3, unit = chunk & 7;
        uint32_t off = row * 128 + unit * 16;
        cp_async16(sBase + A_BY + swz(off), gB + (size_t)row * K + k0 + unit * 8);
    }
}

// common mainloop body; TM = CTA tile height (128 or 64)
template <bool RELU2, bool OUT16, int TM>
__device__ __forceinline__ void gemm_body(
    const __half* __restrict__ A, const __half* __restrict__ B, void* __restrict__ Cv,
    int K, int ldc, int m0, int n0)
{
    extern __shared__ char smem[];
    constexpr int MI = TM / 64;                    // 16-row MMA slabs per warp
    constexpr int A_BY = TM * 128;
    constexpr int STG = A_BY + B_BYTES;
    const uint32_t sb = smem_u32(smem);
    const int tid  = threadIdx.x;
    const int lane = tid & 31;
    const int warp = tid >> 5;
    const int wm = (warp & 3) * (TM / 4);          // warp grid 4x2, warp tile (TM/4)x64
    const int wn = (warp >> 2) * 64;

    const __half* gA = A + (size_t)m0 * K;
    const __half* gB = B + (size_t)n0 * K;
    const int KT = K / BLK_K;

    // prologue: 2 stages in flight
    load_tile_t<TM>(sb, gA, gB, K, 0, tid);
    CP_COMMIT();
    load_tile_t<TM>(sb + STG, gA, gB, K, 1, tid);
    CP_COMMIT();

    // ldmatrix linear offsets (swizzle XOR applied per access)
    const uint32_t xmask = (uint32_t)(lane & 7) << 4;
    uint32_t aLin[MI];
    #pragma unroll
    for (int mi = 0; mi < MI; ++mi)
        aLin[mi] = (uint32_t)(wm + mi * 16 + (lane & 15)) * 128 + (uint32_t)(lane >> 4) * 16;
    uint32_t bLin[4];
    #pragma unroll
    for (int jp = 0; jp < 4; ++jp)
        bLin[jp] = (uint32_t)(wn + jp * 16 + (lane & 15)) * 128 + (uint32_t)(lane >> 4) * 16;

    float c[MI][8][4];
    #pragma unroll
    for (int mi = 0; mi < MI; ++mi)
        #pragma unroll
        for (int j = 0; j < 8; ++j)
            #pragma unroll
            for (int q = 0; q < 4; ++q) c[mi][j][q] = 0.0f;

    int curSt = 0, pfSt = 2;
    for (int kt = 0; kt < KT; ++kt) {
        CP_WAIT1();
        __syncthreads();

        // prefetch k-tile kt+2 into the slot consumed at kt-1
        int nk = kt + 2;
        if (nk < KT) load_tile_t<TM>(sb + pfSt * STG, gA, gB, K, nk, tid);
        CP_COMMIT();
        if (++pfSt == STAGES) pfSt = 0;

        const uint32_t st = sb + curSt * STG;
        if (++curSt == STAGES) curSt = 0;

        #pragma unroll
        for (int s = 0; s < 4; ++s) {              // 4 x K=16 steps (32B each)
            const uint32_t add = s * 32;
            uint32_t a[MI][4], b[4][4];
            #pragma unroll
            for (int mi = 0; mi < MI; ++mi)
                LDSM_X4(a[mi][0], a[mi][1], a[mi][2], a[mi][3], st + ((aLin[mi] + add) ^ xmask));
            #pragma unroll
            for (int jp = 0; jp < 4; ++jp)
                LDSM_X4(b[jp][0], b[jp][1], b[jp][2], b[jp][3],
                        st + A_BY + ((bLin[jp] + add) ^ xmask));
            #pragma unroll
            for (int mi = 0; mi < MI; ++mi)
                #pragma unroll
                for (int jp = 0; jp < 4; ++jp) {
                    MMA_F16(c[mi][2 * jp][0], c[mi][2 * jp][1], c[mi][2 * jp][2], c[mi][2 * jp][3],
                            a[mi][0], a[mi][1], a[mi][2], a[mi][3], b[jp][0], b[jp][2]);
                    MMA_F16(c[mi][2 * jp + 1][0], c[mi][2 * jp + 1][1], c[mi][2 * jp + 1][2], c[mi][2 * jp + 1][3],
                            a[mi][0], a[mi][1], a[mi][2], a[mi][3], b[jp][1], b[jp][3]);
                }
        }
    }

    // epilogue
    const int row0 = m0 + wm + (lane >> 2);
    const int col0 = n0 + wn + (lane & 3) * 2;
    #pragma unroll
    for (int mi = 0; mi < MI; ++mi)
        #pragma unroll
        for (int rr = 0; rr < 2; ++rr) {
            const int row = row0 + mi * 16 + rr * 8;
            #pragma unroll
            for (int j = 0; j < 8; ++j) {
                float v0 = c[mi][j][rr * 2], v1 = c[mi][j][rr * 2 + 1];
                if (RELU2) {
                    v0 = fmaxf(v0, 0.0f); v0 *= v0;
                    v1 = fmaxf(v1, 0.0f); v1 *= v1;
                }
                if (OUT16) {
                    __half* base = (__half*)Cv + (size_t)row * ldc + col0;
                    __half2 hv = __floats2half2_rn(v0, v1);
                    *reinterpret_cast<__half2*>(base + j * 8) = hv;
                } else {
                    float* base = (float*)Cv + (size_t)row * ldc + col0;
                    *reinterpret_cast<float2*>(base + j * 8) = make_float2(v0, v1);
                }
            }
        }
}

// GEMM1: uniform 128x128 tiles, 2D grid
template <bool RELU2, bool OUT16>
__global__ void __launch_bounds__(256, 2) gemm_f16_mma(
    const __half* __restrict__ A, const __half* __restrict__ B,
    void* __restrict__ Cv, int K, int ldc)
{
    gemm_body<RELU2, OUT16, 128>(A, B, Cv, K, ldc, blockIdx.x * 128, blockIdx.y * 128);
}

// GEMM2: mixed tiles — 296 x M128 (rows 0-4735) then 432 x M64 (rows 4736-8191).
// Big tiles get low bids -> placed in wave 1; M64 tiles pack the residual capacity.
__global__ void __launch_bounds__(256, 2) gemm2_f16_mixed(
    const __half* __restrict__ A, const __half* __restrict__ B,
    void* __restrict__ Cv, int K, int ldc)
{
    const int bx = blockIdx.x;
    if (bx < G2_BIG_TILES) {
        gemm_body<false, false, 128>(A, B, Cv, K, ldc, (bx >> 3) * 128, (bx & 7) * 128);
    } else {
        const int i = bx - G2_BIG_TILES;
        gemm_body<false, false, 64>(A, B, Cv, K, ldc, G2_SMALL_ROW0 + (i >> 3) * 64, (i & 7) * 128);
    }
}

// ---------------- fused fp32 -> fp16 RN pre-pass (all three tensors) ----------------
__global__ void to_half_all_kernel(const float4* __restrict__ x,   __half2* __restrict__ xo,
                                   const float4* __restrict__ wf,  __half2* __restrict__ wfo,
                                   const float4* __restrict__ wp,  __half2* __restrict__ wpo)
{
    const int n4x = T_DIM * D_DIM / 4;
    const int n4f = H_DIM * D_DIM / 4;
    const int n4p = D_DIM * H_DIM / 4;
    const int stride = gridDim.x * blockDim.x;
    for (int i = blockIdx.x * blockDim.x + threadIdx.x; i < n4x + n4f + n4p; i += stride) {
        const float4* src; __half2* dst; int j;
        if (i < n4x)            { src = x;  dst = xo;  j = i; }
        else if (i < n4x + n4f) { src = wf; dst = wfo; j = i - n4x; }
        else                    { src = wp; dst = wpo; j = i - n4x - n4f; }
        float4 v = src[j];
        dst[2 * j]     = __floats2half2_rn(v.x, v.y);
        dst[2 * j + 1] = __floats2half2_rn(v.z, v.w);
    }
}

// ---------------- host side ----------------
extern "C" void kernel_launch(void* const* d_in, const int* in_sizes, int n_in,
                              void* d_out, int out_size)
{
    const float* x   = (const float*)d_in[0];  // [8192, 1024]
    const float* wfc = (const float*)d_in[1];  // [4096, 1024]
    const float* wpr = (const float*)d_in[2];  // [1024, 4096]
    float* out = (float*)d_out;                // [8192, 1024]

    __half *h, *xh, *wfch, *wprh;
    cudaGetSymbolAddress((void**)&h,    g_h);
    cudaGetSymbolAddress((void**)&xh,   g_xh);
    cudaGetSymbolAddress((void**)&wfch, g_wfc);
    cudaGetSymbolAddress((void**)&wprh, g_wpr);

    cudaFuncSetAttribute(gemm_f16_mma<true, true>,
                         cudaFuncAttributeMaxDynamicSharedMemorySize, SMEM_TOTAL);
    cudaFuncSetAttribute(gemm2_f16_mixed,
                         cudaFuncAttributeMaxDynamicSharedMemorySize, SMEM_TOTAL);

    // fp32 -> fp16 (RN) pre-pass; fp16 mantissa == tf32 mantissa (11 bits effective)
    to_half_all_kernel<<<2368, 256>>>((const float4*)x,   (__half2*)xh,
                                      (const float4*)wfc, (__half2*)wfch,
                                      (const float4*)wpr, (__half2*)wprh);

    // GEMM1: h = relu(x @ Wfc^T)^2   [8192, 4096], K = 1024, out fp16
    gemm_f16_mma<true, true><<<dim3(T_DIM / 128, H_DIM / BLK_N), 256, SMEM_TOTAL>>>(
        xh, wfch, h, D_DIM, H_DIM);

    // GEMM2: out = h @ Wpr^T         [8192, 1024], K = 4096, out fp32, mixed tiles
    gemm2_f16_mixed<<<728, 256, SMEM_TOTAL>>>(h, wprh, out, H_DIM, D_DIM);
}

// round 12
// speedup vs baseline: 1.5826x; 1.0158x over previous
#include <cuda_runtime.h>
#include <cuda_fp16.h>
#include <cstdint>

// ---------------- problem dims ----------------
#define T_DIM 8192
#define D_DIM 1024
#define H_DIM 4096

// scratch (device globals: no allocation allowed)
__device__ __half g_h  [(size_t)T_DIM * H_DIM];   // 64 MB intermediate (fp16)
__device__ __half g_xh [(size_t)T_DIM * D_DIM];   // fp16 x
__device__ __half g_wfc[(size_t)H_DIM * D_DIM];   // fp16 W_fc
__device__ __half g_wpr[(size_t)D_DIM * H_DIM];   // fp16 W_proj

// ---------------- helpers ----------------
__device__ __forceinline__ uint32_t smem_u32(const void* p) {
    uint32_t a;
    asm("{ .reg .u64 t; cvta.to.shared.u64 t, %1; cvt.u32.u64 %0, t; }" : "=r"(a) : "l"(p));
    return a;
}
__device__ __forceinline__ uint32_t swz(uint32_t b) {   // SW128: XOR bits[6:4] with bits[9:7]
    return b ^ ((b >> 3) & 0x70u);
}
__device__ __forceinline__ void cp_async16(uint32_t saddr, const void* g) {
    asm volatile("cp.async.cg.shared.global [%0], [%1], 16;" :: "r"(saddr), "l"(g));
}
#define CP_COMMIT() asm volatile("cp.async.commit_group;" ::: "memory")
#define CP_WAIT1()  asm volatile("cp.async.wait_group 1;" ::: "memory")

#define LDSM_X4(r0, r1, r2, r3, addr) \
    asm volatile("ldmatrix.sync.aligned.m8n8.x4.shared.b16 {%0,%1,%2,%3}, [%4];" \
        : "=r"(r0), "=r"(r1), "=r"(r2), "=r"(r3) : "r"(addr))

// fp16 MMA, fp32 accumulate: D(16x8) += A(16x16) * B(16x8)
#define MMA_F16(c0, c1, c2, c3, a0, a1, a2, a3, b0, b1) \
    asm volatile("mma.sync.aligned.m16n8k16.row.col.f32.f16.f16.f32 " \
        "{%0,%1,%2,%3}, {%4,%5,%6,%7}, {%8,%9}, {%0,%1,%2,%3};" \
        : "+f"(c0), "+f"(c1), "+f"(c2), "+f"(c3) \
        : "r"(a0), "r"(a1), "r"(a2), "r"(a3), "r"(b0), "r"(b1))

// ---------------- GEMM config ----------------
static constexpr int BLK_N = 128;
static constexpr int BLK_K = 64;                 // fp16 elems -> 128 bytes per row
static constexpr int STAGES = 3;                 // <=96KB -> 2 CTAs / SM
static constexpr int B_BYTES = BLK_N * BLK_K * 2;          // 16384
static constexpr int SMEM_TOTAL = STAGES * (128 * 128 + B_BYTES);   // 98304 (TM=128 worst case)

// GEMM1 mixed split: 1760 M128 tiles (rows 0-7039, 55x32) + 576 M64 (rows 7040-8191, 18x32)
static constexpr int G1_BIG_TILES = 1760;
static constexpr int G1_SMALL_ROW0 = 7040;
// GEMM2 mixed split: 296 M128 tiles (rows 0-4735) + 432 M64 tiles (rows 4736-8191)
static constexpr int G2_BIG_TILES = 296;
static constexpr int G2_SMALL_ROW0 = 4736;

// load one TMx64 A tile + 128x64 B tile (fp16) into stage at sBase
template <int TM>
__device__ __forceinline__ void load_tile_t(uint32_t sBase, const __half* __restrict__ gA,
                                            const __half* __restrict__ gB, int K, int kt, int tid)
{
    const int k0 = kt * BLK_K;
    constexpr int A_BY = TM * 128;
    #pragma unroll
    for (int i = 0; i < TM * 8 / 256; ++i) {       // A: TM*8 x 16B chunks / 256 thr
        int chunk = tid + i * 256;
        int row = chunk >> 3, unit = chunk & 7;    // 8 x 16B units per 128B row
        uint32_t off = row * 128 + unit * 16;
        cp_async16(sBase + swz(off), gA + (size_t)row * K + k0 + unit * 8);
    }
    #pragma unroll
    for (int i = 0; i < 4; ++i) {                  // B
        int chunk = tid + i * 256;
        int row = chunk >> 3, unit = chunk & 7;
        uint32_t off = row * 128 + unit * 16;
        cp_async16(sBase + A_BY + swz(off), gB + (size_t)row * K + k0 + unit * 8);
    }
}

// common mainloop body
// TM = CTA tile height; WGM = warp-grid M dimension (8 warps as WGM x (8/WGM))
// warp tile = (TM/WGM) x (16*WGM);  MI = TM/(16*WGM) m-slabs, NJ = WGM n-groups of 16
template <bool RELU2, bool OUT16, int TM, int WGM>
__device__ __forceinline__ void gemm_body(
    const __half* __restrict__ A, const __half* __restrict__ B, void* __restrict__ Cv,
    int K, int ldc, int m0, int n0)
{
    extern __shared__ char smem[];
    constexpr int MI = TM / (16 * WGM);
    constexpr int NJ = WGM;
    constexpr int A_BY = TM * 128;
    constexpr int STG = A_BY + B_BYTES;
    const uint32_t sb = smem_u32(smem);
    const int tid  = threadIdx.x;
    const int lane = tid & 31;
    const int warp = tid >> 5;
    const int wm = (warp % WGM) * (TM / WGM);
    const int wn = (warp / WGM) * (16 * WGM);

    const __half* gA = A + (size_t)m0 * K;
    const __half* gB = B + (size_t)n0 * K;
    const int KT = K / BLK_K;

    // prologue: 2 stages in flight
    load_tile_t<TM>(sb, gA, gB, K, 0, tid);
    CP_COMMIT();
    load_tile_t<TM>(sb + STG, gA, gB, K, 1, tid);
    CP_COMMIT();

    // ldmatrix linear offsets (swizzle XOR applied per access)
    const uint32_t xmask = (uint32_t)(lane & 7) << 4;
    uint32_t aLin[MI];
    #pragma unroll
    for (int mi = 0; mi < MI; ++mi)
        aLin[mi] = (uint32_t)(wm + mi * 16 + (lane & 15)) * 128 + (uint32_t)(lane >> 4) * 16;
    uint32_t bLin[NJ];
    #pragma unroll
    for (int jp = 0; jp < NJ; ++jp)
        bLin[jp] = (uint32_t)(wn + jp * 16 + (lane & 15)) * 128 + (uint32_t)(lane >> 4) * 16;

    float c[MI][2 * NJ][4];
    #pragma unroll
    for (int mi = 0; mi < MI; ++mi)
        #pragma unroll
        for (int j = 0; j < 2 * NJ; ++j)
            #pragma unroll
            for (int q = 0; q < 4; ++q) c[mi][j][q] = 0.0f;

    int curSt = 0, pfSt = 2;
    for (int kt = 0; kt < KT; ++kt) {
        CP_WAIT1();
        __syncthreads();

        // prefetch k-tile kt+2 into the slot consumed at kt-1
        int nk = kt + 2;
        if (nk < KT) load_tile_t<TM>(sb + pfSt * STG, gA, gB, K, nk, tid);
        CP_COMMIT();
        if (++pfSt == STAGES) pfSt = 0;

        const uint32_t st = sb + curSt * STG;
        if (++curSt == STAGES) curSt = 0;

        #pragma unroll
        for (int s = 0; s < 4; ++s) {              // 4 x K=16 steps (32B each)
            const uint32_t add = s * 32;
            uint32_t a[MI][4], b[NJ][4];
            #pragma unroll
            for (int mi = 0; mi < MI; ++mi)
                LDSM_X4(a[mi][0], a[mi][1], a[mi][2], a[mi][3], st + ((aLin[mi] + add) ^ xmask));
            #pragma unroll
            for (int jp = 0; jp < NJ; ++jp)
                LDSM_X4(b[jp][0], b[jp][1], b[jp][2], b[jp][3],
                        st + A_BY + ((bLin[jp] + add) ^ xmask));
            #pragma unroll
            for (int mi = 0; mi < MI; ++mi)
                #pragma unroll
                for (int jp = 0; jp < NJ; ++jp) {
                    MMA_F16(c[mi][2 * jp][0], c[mi][2 * jp][1], c[mi][2 * jp][2], c[mi][2 * jp][3],
                            a[mi][0], a[mi][1], a[mi][2], a[mi][3], b[jp][0], b[jp][2]);
                    MMA_F16(c[mi][2 * jp + 1][0], c[mi][2 * jp + 1][1], c[mi][2 * jp + 1][2], c[mi][2 * jp + 1][3],
                            a[mi][0], a[mi][1], a[mi][2], a[mi][3], b[jp][1], b[jp][3]);
                }
        }
    }

    // epilogue
    const int row0 = m0 + wm + (lane >> 2);
    const int col0 = n0 + wn + (lane & 3) * 2;
    #pragma unroll
    for (int mi = 0; mi < MI; ++mi)
        #pragma unroll
        for (int rr = 0; rr < 2; ++rr) {
            const int row = row0 + mi * 16 + rr * 8;
            #pragma unroll
            for (int j = 0; j < 2 * NJ; ++j) {
                float v0 = c[mi][j][rr * 2], v1 = c[mi][j][rr * 2 + 1];
                if (RELU2) {
                    v0 = fmaxf(v0, 0.0f); v0 *= v0;
                    v1 = fmaxf(v1, 0.0f); v1 *= v1;
                }
                if (OUT16) {
                    __half* base = (__half*)Cv + (size_t)row * ldc + col0;
                    __half2 hv = __floats2half2_rn(v0, v1);
                    *reinterpret_cast<__half2*>(base + j * 8) = hv;
                } else {
                    float* base = (float*)Cv + (size_t)row * ldc + col0;
                    *reinterpret_cast<float2*>(base + j * 8) = make_float2(v0, v1);
                }
            }
        }
}

// GEMM1: mixed tiles — 1760 x M128 (rows 0-7039) then 576 x M64 (rows 7040-8191)
__global__ void __launch_bounds__(256, 2) gemm1_f16_mixed(
    const __half* __restrict__ A, const __half* __restrict__ B,
    void* __restrict__ Cv, int K, int ldc)
{
    const int bx = blockIdx.x;
    if (bx < G1_BIG_TILES) {
        gemm_body<true, true, 128, 4>(A, B, Cv, K, ldc, (bx >> 5) * 128, (bx & 31) * 128);
    } else {
        const int i = bx - G1_BIG_TILES;
        gemm_body<true, true, 64, 2>(A, B, Cv, K, ldc, G1_SMALL_ROW0 + (i >> 5) * 64, (i & 31) * 128);
    }
}

// GEMM2: mixed tiles — 296 x M128 (rows 0-4735) then 432 x M64 (rows 4736-8191)
__global__ void __launch_bounds__(256, 2) gemm2_f16_mixed(
    const __half* __restrict__ A, const __half* __restrict__ B,
    void* __restrict__ Cv, int K, int ldc)
{
    const int bx = blockIdx.x;
    if (bx < G2_BIG_TILES) {
        gemm_body<false, false, 128, 4>(A, B, Cv, K, ldc, (bx >> 3) * 128, (bx & 7) * 128);
    } else {
        const int i = bx - G2_BIG_TILES;
        gemm_body<false, false, 64, 2>(A, B, Cv, K, ldc, G2_SMALL_ROW0 + (i >> 3) * 64, (i & 7) * 128);
    }
}

// ---------------- fused fp32 -> fp16 RN pre-pass (block-partitioned regions) ----------------
// blocks [0,1184): x (2M float4); [1184,1776): wfc (1M); [1776,2368): wpr (1M)
__global__ void to_half_all_kernel(const float4* __restrict__ x,   __half2* __restrict__ xo,
                                   const float4* __restrict__ wf,  __half2* __restrict__ wfo,
                                   const float4* __restrict__ wp,  __half2* __restrict__ wpo)
{
    const float4* src; __half2* dst; int n4, b0, nb;
    if (blockIdx.x < 1184)      { src = x;  dst = xo;  n4 = T_DIM * D_DIM / 4; b0 = 0;    nb = 1184; }
    else if (blockIdx.x < 1776) { src = wf; dst = wfo; n4 = H_DIM * D_DIM / 4; b0 = 1184; nb = 592; }
    else                        { src = wp; dst = wpo; n4 = D_DIM * H_DIM / 4; b0 = 1776; nb = 592; }
    const int stride = nb * 256;
    #pragma unroll 2
    for (int i = (blockIdx.x - b0) * 256 + threadIdx.x; i < n4; i += stride) {
        float4 v = src[i];
        dst[2 * i]     = __floats2half2_rn(v.x, v.y);
        dst[2 * i + 1] = __floats2half2_rn(v.z, v.w);
    }
}

// ---------------- host side ----------------
extern "C" void kernel_launch(void* const* d_in, const int* in_sizes, int n_in,
                              void* d_out, int out_size)
{
    const float* x   = (const float*)d_in[0];  // [8192, 1024]
    const float* wfc = (const float*)d_in[1];  // [4096, 1024]
    const float* wpr = (const float*)d_in[2];  // [1024, 4096]
    float* out = (float*)d_out;                // [8192, 1024]

    __half *h, *xh, *wfch, *wprh;
    cudaGetSymbolAddress((void**)&h,    g_h);
    cudaGetSymbolAddress((void**)&xh,   g_xh);
    cudaGetSymbolAddress((void**)&wfch, g_wfc);
    cudaGetSymbolAddress((void**)&wprh, g_wpr);

    cudaFuncSetAttribute(gemm1_f16_mixed,
                         cudaFuncAttributeMaxDynamicSharedMemorySize, SMEM_TOTAL);
    cudaFuncSetAttribute(gemm2_f16_mixed,
                         cudaFuncAttributeMaxDynamicSharedMemorySize, SMEM_TOTAL);

    // fp32 -> fp16 (RN) pre-pass; fp16 mantissa == tf32 mantissa (11 bits effective)
    to_half_all_kernel<<<2368, 256>>>((const float4*)x,   (__half2*)xh,
                                      (const float4*)wfc, (__half2*)wfch,
                                      (const float4*)wpr, (__half2*)wprh);

    // GEMM1: h = relu(x @ Wfc^T)^2   [8192, 4096], K = 1024, out fp16, mixed tiles
    gemm1_f16_mixed<<<G1_BIG_TILES + 576, 256, SMEM_TOTAL>>>(xh, wfch, h, D_DIM, H_DIM);

    // GEMM2: out = h @ Wpr^T         [8192, 1024], K = 4096, out fp32, mixed tiles
    gemm2_f16_mixed<<<G2_BIG_TILES + 432, 256, SMEM_TOTAL>>>(h, wprh, out, H_DIM, D_DIM);
}

// round 13
// speedup vs baseline: 1.5856x; 1.0019x over previous
#include <cuda_runtime.h>
#include <cuda_fp16.h>
#include <cstdint>

// ---------------- problem dims ----------------
#define T_DIM 8192
#define D_DIM 1024
#define H_DIM 4096

// scratch (device globals: no allocation allowed)
__device__ __half g_h  [(size_t)T_DIM * H_DIM];   // 64 MB intermediate (fp16)
__device__ __half g_xh [(size_t)T_DIM * D_DIM];   // fp16 x
__device__ __half g_wfc[(size_t)H_DIM * D_DIM];   // fp16 W_fc
__device__ __half g_wpr[(size_t)D_DIM * H_DIM];   // fp16 W_proj

// ---------------- helpers ----------------
__device__ __forceinline__ uint32_t smem_u32(const void* p) {
    uint32_t a;
    asm("{ .reg .u64 t; cvta.to.shared.u64 t, %1; cvt.u32.u64 %0, t; }" : "=r"(a) : "l"(p));
    return a;
}
__device__ __forceinline__ uint32_t swz(uint32_t b) {   // SW128: XOR bits[6:4] with bits[9:7]
    return b ^ ((b >> 3) & 0x70u);
}
__device__ __forceinline__ void cp_async16(uint32_t saddr, const void* g) {
    asm volatile("cp.async.cg.shared.global [%0], [%1], 16;" :: "r"(saddr), "l"(g));
}
#define CP_COMMIT() asm volatile("cp.async.commit_group;" ::: "memory")
#define CP_WAIT1()  asm volatile("cp.async.wait_group 1;" ::: "memory")

#define LDSM_X4(r0, r1, r2, r3, addr) \
    asm volatile("ldmatrix.sync.aligned.m8n8.x4.shared.b16 {%0,%1,%2,%3}, [%4];" \
        : "=r"(r0), "=r"(r1), "=r"(r2), "=r"(r3) : "r"(addr))

// fp16 MMA, fp32 accumulate: D(16x8) += A(16x16) * B(16x8)
#define MMA_F16(c0, c1, c2, c3, a0, a1, a2, a3, b0, b1) \
    asm volatile("mma.sync.aligned.m16n8k16.row.col.f32.f16.f16.f32 " \
        "{%0,%1,%2,%3}, {%4,%5,%6,%7}, {%8,%9}, {%0,%1,%2,%3};" \
        : "+f"(c0), "+f"(c1), "+f"(c2), "+f"(c3) \
        : "r"(a0), "r"(a1), "r"(a2), "r"(a3), "r"(b0), "r"(b1))

// ---------------- GEMM config ----------------
static constexpr int BLK_N = 128;
static constexpr int BLK_K = 64;                 // fp16 elems -> 128 bytes per row
static constexpr int STAGES = 3;                 // <=96KB -> 2 CTAs / SM
static constexpr int B_BYTES = BLK_N * BLK_K * 2;          // 16384
static constexpr int SMEM_TOTAL = STAGES * (128 * 128 + B_BYTES);   // 98304 (TM=128 worst case)

// GEMM1 mixed split: 1760 M128 tiles (rows 0-7039, 55x32) + 576 M64 (rows 7040-8191, 18x32)
static constexpr int G1_BIG_TILES = 1760;
static constexpr int G1_SMALL_ROW0 = 7040;
// GEMM2 mixed split: 296 M128 tiles (rows 0-4735) + 432 M64 tiles (rows 4736-8191)
static constexpr int G2_BIG_TILES = 296;
static constexpr int G2_SMALL_ROW0 = 4736;

// load one TMx64 A tile + 128x64 B tile (fp16) into stage at sBase
template <int TM>
__device__ __forceinline__ void load_tile_t(uint32_t sBase, const __half* __restrict__ gA,
                                            const __half* __restrict__ gB, int K, int kt, int tid)
{
    const int k0 = kt * BLK_K;
    constexpr int A_BY = TM * 128;
    #pragma unroll
    for (int i = 0; i < TM * 8 / 256; ++i) {       // A: TM*8 x 16B chunks / 256 thr
        int chunk = tid + i * 256;
        int row = chunk >> 3, unit = chunk & 7;    // 8 x 16B units per 128B row
        uint32_t off = row * 128 + unit * 16;
        cp_async16(sBase + swz(off), gA + (size_t)row * K + k0 + unit * 8);
    }
    #pragma unroll
    for (int i = 0; i < 4; ++i) {                  // B
        int chunk = tid + i * 256;
        int row = chunk >> 3, unit = chunk & 7;
        uint32_t off = row * 128 + unit * 16;
        cp_async16(sBase + A_BY + swz(off), gB + (size_t)row * K + k0 + unit * 8);
    }
}

// common mainloop body
// TM = CTA tile height; WGM = warp-grid M dimension (8 warps as WGM x (8/WGM))
// warp tile = (TM/WGM) x (16*WGM);  MI = TM/(16*WGM) m-slabs, NJ = WGM n-groups of 16
template <bool RELU2, bool OUT16, int TM, int WGM>
__device__ __forceinline__ void gemm_body(
    const __half* __restrict__ A, const __half* __restrict__ B, void* __restrict__ Cv,
    int K, int ldc, int m0, int n0)
{
    extern __shared__ char smem[];
    constexpr int MI = TM / (16 * WGM);
    constexpr int NJ = WGM;
    constexpr int A_BY = TM * 128;
    constexpr int STG = A_BY + B_BYTES;
    const uint32_t sb = smem_u32(smem);
    const int tid  = threadIdx.x;
    const int lane = tid & 31;
    const int warp = tid >> 5;
    const int wm = (warp % WGM) * (TM / WGM);
    const int wn = (warp / WGM) * (16 * WGM);

    const __half* gA = A + (size_t)m0 * K;
    const __half* gB = B + (size_t)n0 * K;
    const int KT = K / BLK_K;

    // prologue: 2 stages in flight
    load_tile_t<TM>(sb, gA, gB, K, 0, tid);
    CP_COMMIT();
    load_tile_t<TM>(sb + STG, gA, gB, K, 1, tid);
    CP_COMMIT();

    // ldmatrix linear offsets (swizzle XOR applied per access)
    const uint32_t xmask = (uint32_t)(lane & 7) << 4;
    uint32_t aLin[MI];
    #pragma unroll
    for (int mi = 0; mi < MI; ++mi)
        aLin[mi] = (uint32_t)(wm + mi * 16 + (lane & 15)) * 128 + (uint32_t)(lane >> 4) * 16;
    uint32_t bLin[NJ];
    #pragma unroll
    for (int jp = 0; jp < NJ; ++jp)
        bLin[jp] = (uint32_t)(wn + jp * 16 + (lane & 15)) * 128 + (uint32_t)(lane >> 4) * 16;

    float c[MI][2 * NJ][4];
    #pragma unroll
    for (int mi = 0; mi < MI; ++mi)
        #pragma unroll
        for (int j = 0; j < 2 * NJ; ++j)
            #pragma unroll
            for (int q = 0; q < 4; ++q) c[mi][j][q] = 0.0f;

    int curSt = 0, pfSt = 2;
    for (int kt = 0; kt < KT; ++kt) {
        CP_WAIT1();
        __syncthreads();

        // prefetch k-tile kt+2 into the slot consumed at kt-1
        int nk = kt + 2;
        if (nk < KT) load_tile_t<TM>(sb + pfSt * STG, gA, gB, K, nk, tid);
        CP_COMMIT();
        if (++pfSt == STAGES) pfSt = 0;

        const uint32_t st = sb + curSt * STG;
        if (++curSt == STAGES) curSt = 0;

        #pragma unroll
        for (int s = 0; s < 4; ++s) {              // 4 x K=16 steps (32B each)
            const uint32_t add = s * 32;
            uint32_t a[MI][4], b[NJ][4];
            #pragma unroll
            for (int mi = 0; mi < MI; ++mi)
                LDSM_X4(a[mi][0], a[mi][1], a[mi][2], a[mi][3], st + ((aLin[mi] + add) ^ xmask));
            #pragma unroll
            for (int jp = 0; jp < NJ; ++jp)
                LDSM_X4(b[jp][0], b[jp][1], b[jp][2], b[jp][3],
                        st + A_BY + ((bLin[jp] + add) ^ xmask));
            #pragma unroll
            for (int mi = 0; mi < MI; ++mi)
                #pragma unroll
                for (int jp = 0; jp < NJ; ++jp) {
                    MMA_F16(c[mi][2 * jp][0], c[mi][2 * jp][1], c[mi][2 * jp][2], c[mi][2 * jp][3],
                            a[mi][0], a[mi][1], a[mi][2], a[mi][3], b[jp][0], b[jp][2]);
                    MMA_F16(c[mi][2 * jp + 1][0], c[mi][2 * jp + 1][1], c[mi][2 * jp + 1][2], c[mi][2 * jp + 1][3],
                            a[mi][0], a[mi][1], a[mi][2], a[mi][3], b[jp][1], b[jp][3]);
                }
        }
    }

    // epilogue
    const int row0 = m0 + wm + (lane >> 2);
    const int col0 = n0 + wn + (lane & 3) * 2;
    #pragma unroll
    for (int mi = 0; mi < MI; ++mi)
        #pragma unroll
        for (int rr = 0; rr < 2; ++rr) {
            const int row = row0 + mi * 16 + rr * 8;
            #pragma unroll
            for (int j = 0; j < 2 * NJ; ++j) {
                float v0 = c[mi][j][rr * 2], v1 = c[mi][j][rr * 2 + 1];
                if (RELU2) {
                    v0 = fmaxf(v0, 0.0f); v0 *= v0;
                    v1 = fmaxf(v1, 0.0f); v1 *= v1;
                }
                if (OUT16) {
                    __half* base = (__half*)Cv + (size_t)row * ldc + col0;
                    __half2 hv = __floats2half2_rn(v0, v1);
                    *reinterpret_cast<__half2*>(base + j * 8) = hv;
                } else {
                    float* base = (float*)Cv + (size_t)row * ldc + col0;
                    *reinterpret_cast<float2*>(base + j * 8) = make_float2(v0, v1);
                }
            }
        }
}

// GEMM1: mixed tiles — 1760 x M128 (rows 0-7039) then 576 x M64 (rows 7040-8191)
__global__ void __launch_bounds__(256, 2) gemm1_f16_mixed(
    const __half* __restrict__ A, const __half* __restrict__ B,
    void* __restrict__ Cv, int K, int ldc)
{
    const int bx = blockIdx.x;
    if (bx < G1_BIG_TILES) {
        gemm_body<true, true, 128, 4>(A, B, Cv, K, ldc, (bx >> 5) * 128, (bx & 31) * 128);
    } else {
        const int i = bx - G1_BIG_TILES;
        gemm_body<true, true, 64, 2>(A, B, Cv, K, ldc, G1_SMALL_ROW0 + (i >> 5) * 64, (i & 31) * 128);
    }
}

// GEMM2: mixed tiles — 296 x M128 (rows 0-4735) then 432 x M64 (rows 4736-8191)
__global__ void __launch_bounds__(256, 2) gemm2_f16_mixed(
    const __half* __restrict__ A, const __half* __restrict__ B,
    void* __restrict__ Cv, int K, int ldc)
{
    const int bx = blockIdx.x;
    if (bx < G2_BIG_TILES) {
        gemm_body<false, false, 128, 4>(A, B, Cv, K, ldc, (bx >> 3) * 128, (bx & 7) * 128);
    } else {
        const int i = bx - G2_BIG_TILES;
        gemm_body<false, false, 64, 2>(A, B, Cv, K, ldc, G2_SMALL_ROW0 + (i >> 3) * 64, (i & 7) * 128);
    }
}

// ---------------- fused fp32 -> fp16 RN pre-pass (MLP=4 panels, exact divisibility) ----------------
// blocks [0,512): x (2M float4, 4 iters); [512,768): wfc (1M, 4 iters); [768,1024): wpr (1M, 4 iters)
// Each block iteration covers 1024 float4 (4 strided coalesced loads per thread, all independent).
__global__ void to_half_all_kernel(const float4* __restrict__ x,   __half2* __restrict__ xo,
                                   const float4* __restrict__ wf,  __half2* __restrict__ wfo,
                                   const float4* __restrict__ wp,  __half2* __restrict__ wpo)
{
    const float4* src; __half2* dst; int rb, nb;
    if (blockIdx.x < 512)       { src = x;  dst = xo;  rb = blockIdx.x;       nb = 512; }
    else if (blockIdx.x < 768)  { src = wf; dst = wfo; rb = blockIdx.x - 512; nb = 256; }
    else                        { src = wp; dst = wpo; rb = blockIdx.x - 768; nb = 256; }
    // region size = nb * 1024 * 4 float4 exactly (x: 2M, wfc/wpr: 1M)
    #pragma unroll
    for (int it = 0; it < 4; ++it) {
        const int base = (it * nb + rb) * 1024 + threadIdx.x;
        float4 v0 = src[base];
        float4 v1 = src[base + 256];
        float4 v2 = src[base + 512];
        float4 v3 = src[base + 768];
        dst[2 * base]             = __floats2half2_rn(v0.x, v0.y);
        dst[2 * base + 1]         = __floats2half2_rn(v0.z, v0.w);
        dst[2 * (base + 256)]     = __floats2half2_rn(v1.x, v1.y);
        dst[2 * (base + 256) + 1] = __floats2half2_rn(v1.z, v1.w);
        dst[2 * (base + 512)]     = __floats2half2_rn(v2.x, v2.y);
        dst[2 * (base + 512) + 1] = __floats2half2_rn(v2.z, v2.w);
        dst[2 * (base + 768)]     = __floats2half2_rn(v3.x, v3.y);
        dst[2 * (base + 768) + 1] = __floats2half2_rn(v3.z, v3.w);
    }
}

// ---------------- host side ----------------
extern "C" void kernel_launch(void* const* d_in, const int* in_sizes, int n_in,
                              void* d_out, int out_size)
{
    const float* x   = (const float*)d_in[0];  // [8192, 1024]
    const float* wfc = (const float*)d_in[1];  // [4096, 1024]
    const float* wpr = (const float*)d_in[2];  // [1024, 4096]
    float* out = (float*)d_out;                // [8192, 1024]

    __half *h, *xh, *wfch, *wprh;
    cudaGetSymbolAddress((void**)&h,    g_h);
    cudaGetSymbolAddress((void**)&xh,   g_xh);
    cudaGetSymbolAddress((void**)&wfch, g_wfc);
    cudaGetSymbolAddress((void**)&wprh, g_wpr);

    cudaFuncSetAttribute(gemm1_f16_mixed,
                         cudaFuncAttributeMaxDynamicSharedMemorySize, SMEM_TOTAL);
    cudaFuncSetAttribute(gemm2_f16_mixed,
                         cudaFuncAttributeMaxDynamicSharedMemorySize, SMEM_TOTAL);

    // fp32 -> fp16 (RN) pre-pass; fp16 mantissa == tf32 mantissa (11 bits effective)
    to_half_all_kernel<<<1024, 256>>>((const float4*)x,   (__half2*)xh,
                                      (const float4*)wfc, (__half2*)wfch,
                                      (const float4*)wpr, (__half2*)wprh);

    // GEMM1: h = relu(x @ Wfc^T)^2   [8192, 4096], K = 1024, out fp16, mixed tiles
    gemm1_f16_mixed<<<G1_BIG_TILES + 576, 256, SMEM_TOTAL>>>(xh, wfch, h, D_DIM, H_DIM);

    // GEMM2: out = h @ Wpr^T         [8192, 1024], K = 4096, out fp32, mixed tiles
    gemm2_f16_mixed<<<G2_BIG_TILES + 432, 256, SMEM_TOTAL>>>(h, wprh, out, H_DIM, D_DIM);
}

// round 14
// speedup vs baseline: 1.6008x; 1.0096x over previous
#include <cuda_runtime.h>
#include <cuda_fp16.h>
#include <cstdint>

// ---------------- problem dims ----------------
#define T_DIM 8192
#define D_DIM 1024
#define H_DIM 4096

// scratch (device globals: no allocation allowed)
__device__ __half g_h  [(size_t)T_DIM * H_DIM];   // 64 MB intermediate (fp16)
__device__ __half g_xh [(size_t)T_DIM * D_DIM];   // fp16 x
__device__ __half g_wfc[(size_t)H_DIM * D_DIM];   // fp16 W_fc
__device__ __half g_wpr[(size_t)D_DIM * H_DIM];   // fp16 W_proj
__device__ int    g_cnt[128];                     // per-64-row-band completion counters (h)

// ---------------- helpers ----------------
__device__ __forceinline__ uint32_t smem_u32(const void* p) {
    uint32_t a;
    asm("{ .reg .u64 t; cvta.to.shared.u64 t, %1; cvt.u32.u64 %0, t; }" : "=r"(a) : "l"(p));
    return a;
}
__device__ __forceinline__ uint32_t swz(uint32_t b) {   // SW128: XOR bits[6:4] with bits[9:7]
    return b ^ ((b >> 3) & 0x70u);
}
__device__ __forceinline__ void cp_async16(uint32_t saddr, const void* g) {
    asm volatile("cp.async.cg.shared.global [%0], [%1], 16;" :: "r"(saddr), "l"(g));
}
#define CP_COMMIT() asm volatile("cp.async.commit_group;" ::: "memory")
#define CP_WAIT1()  asm volatile("cp.async.wait_group 1;" ::: "memory")

#define LDSM_X4(r0, r1, r2, r3, addr) \
    asm volatile("ldmatrix.sync.aligned.m8n8.x4.shared.b16 {%0,%1,%2,%3}, [%4];" \
        : "=r"(r0), "=r"(r1), "=r"(r2), "=r"(r3) : "r"(addr))

// fp16 MMA, fp32 accumulate: D(16x8) += A(16x16) * B(16x8)
#define MMA_F16(c0, c1, c2, c3, a0, a1, a2, a3, b0, b1) \
    asm volatile("mma.sync.aligned.m16n8k16.row.col.f32.f16.f16.f32 " \
        "{%0,%1,%2,%3}, {%4,%5,%6,%7}, {%8,%9}, {%0,%1,%2,%3};" \
        : "+f"(c0), "+f"(c1), "+f"(c2), "+f"(c3) \
        : "r"(a0), "r"(a1), "r"(a2), "r"(a3), "r"(b0), "r"(b1))

// ---------------- GEMM config ----------------
static constexpr int BLK_N = 128;
static constexpr int BLK_K = 64;                 // fp16 elems -> 128 bytes per row
static constexpr int STAGES = 3;                 // <=96KB -> 2 CTAs / SM
static constexpr int B_BYTES = BLK_N * BLK_K * 2;          // 16384
static constexpr int SMEM_TOTAL = STAGES * (128 * 128 + B_BYTES);   // 98304 (TM=128 worst case)

// GEMM1 mixed split: 1760 M128 tiles (rows 0-7039, 55x32) + 576 M64 (rows 7040-8191, 18x32)
static constexpr int G1_BIG_TILES = 1760;
static constexpr int G1_SMALL_ROW0 = 7040;
static constexpr int G1_TOTAL = 2336;
// GEMM2 mixed split: 296 M128 tiles (rows 0-4735) + 432 M64 tiles (rows 4736-8191)
static constexpr int G2_BIG_TILES = 296;
static constexpr int G2_SMALL_ROW0 = 4736;
static constexpr int G2_TOTAL = 728;

// load one TMx64 A tile + 128x64 B tile (fp16) into stage at sBase
template <int TM>
__device__ __forceinline__ void load_tile_t(uint32_t sBase, const __half* __restrict__ gA,
                                            const __half* __restrict__ gB, int K, int kt, int tid)
{
    const int k0 = kt * BLK_K;
    constexpr int A_BY = TM * 128;
    #pragma unroll
    for (int i = 0; i < TM * 8 / 256; ++i) {       // A: TM*8 x 16B chunks / 256 thr
        int chunk = tid + i * 256;
        int row = chunk >> 3, unit = chunk & 7;    // 8 x 16B units per 128B row
        uint32_t off = row * 128 + unit * 16;
        cp_async16(sBase + swz(off), gA + (size_t)row * K + k0 + unit * 8);
    }
    #pragma unroll
    for (int i = 0; i < 4; ++i) {                  // B
        int chunk = tid + i * 256;
        int row = chunk >> 3, unit = chunk & 7;
        uint32_t off = row * 128 + unit * 16;
        cp_async16(sBase + A_BY + swz(off), gB + (size_t)row * K + k0 + unit * 8);
    }
}

// common mainloop body
// TM = CTA tile height; WGM = warp-grid M dimension (8 warps as WGM x (8/WGM))
template <bool RELU2, bool OUT16, int TM, int WGM>
__device__ __forceinline__ void gemm_body(
    const __half* __restrict__ A, const __half* __restrict__ B, void* __restrict__ Cv,
    int K, int ldc, int m0, int n0)
{
    extern __shared__ char smem[];
    constexpr int MI = TM / (16 * WGM);
    constexpr int NJ = WGM;
    constexpr int A_BY = TM * 128;
    constexpr int STG = A_BY + B_BYTES;
    const uint32_t sb = smem_u32(smem);
    const int tid  = threadIdx.x;
    const int lane = tid & 31;
    const int warp = tid >> 5;
    const int wm = (warp % WGM) * (TM / WGM);
    const int wn = (warp / WGM) * (16 * WGM);

    const __half* gA = A + (size_t)m0 * K;
    const __half* gB = B + (size_t)n0 * K;
    const int KT = K / BLK_K;

    // prologue: 2 stages in flight
    load_tile_t<TM>(sb, gA, gB, K, 0, tid);
    CP_COMMIT();
    load_tile_t<TM>(sb + STG, gA, gB, K, 1, tid);
    CP_COMMIT();

    // ldmatrix linear offsets (swizzle XOR applied per access)
    const uint32_t xmask = (uint32_t)(lane & 7) << 4;
    uint32_t aLin[MI];
    #pragma unroll
    for (int mi = 0; mi < MI; ++mi)
        aLin[mi] = (uint32_t)(wm + mi * 16 + (lane & 15)) * 128 + (uint32_t)(lane >> 4) * 16;
    uint32_t bLin[NJ];
    #pragma unroll
    for (int jp = 0; jp < NJ; ++jp)
        bLin[jp] = (uint32_t)(wn + jp * 16 + (lane & 15)) * 128 + (uint32_t)(lane >> 4) * 16;

    float c[MI][2 * NJ][4];
    #pragma unroll
    for (int mi = 0; mi < MI; ++mi)
        #pragma unroll
        for (int j = 0; j < 2 * NJ; ++j)
            #pragma unroll
            for (int q = 0; q < 4; ++q) c[mi][j][q] = 0.0f;

    int curSt = 0, pfSt = 2;
    for (int kt = 0; kt < KT; ++kt) {
        CP_WAIT1();
        __syncthreads();

        // prefetch k-tile kt+2 into the slot consumed at kt-1
        int nk = kt + 2;
        if (nk < KT) load_tile_t<TM>(sb + pfSt * STG, gA, gB, K, nk, tid);
        CP_COMMIT();
        if (++pfSt == STAGES) pfSt = 0;

        const uint32_t st = sb + curSt * STG;
        if (++curSt == STAGES) curSt = 0;

        #pragma unroll
        for (int s = 0; s < 4; ++s) {              // 4 x K=16 steps (32B each)
            const uint32_t add = s * 32;
            uint32_t a[MI][4], b[NJ][4];
            #pragma unroll
            for (int mi = 0; mi < MI; ++mi)
                LDSM_X4(a[mi][0], a[mi][1], a[mi][2], a[mi][3], st + ((aLin[mi] + add) ^ xmask));
            #pragma unroll
            for (int jp = 0; jp < NJ; ++jp)
                LDSM_X4(b[jp][0], b[jp][1], b[jp][2], b[jp][3],
                        st + A_BY + ((bLin[jp] + add) ^ xmask));
            #pragma unroll
            for (int mi = 0; mi < MI; ++mi)
                #pragma unroll
                for (int jp = 0; jp < NJ; ++jp) {
                    MMA_F16(c[mi][2 * jp][0], c[mi][2 * jp][1], c[mi][2 * jp][2], c[mi][2 * jp][3],
                            a[mi][0], a[mi][1], a[mi][2], a[mi][3], b[jp][0], b[jp][2]);
                    MMA_F16(c[mi][2 * jp + 1][0], c[mi][2 * jp + 1][1], c[mi][2 * jp + 1][2], c[mi][2 * jp + 1][3],
                            a[mi][0], a[mi][1], a[mi][2], a[mi][3], b[jp][1], b[jp][3]);
                }
        }
    }

    // epilogue
    const int row0 = m0 + wm + (lane >> 2);
    const int col0 = n0 + wn + (lane & 3) * 2;
    #pragma unroll
    for (int mi = 0; mi < MI; ++mi)
        #pragma unroll
        for (int rr = 0; rr < 2; ++rr) {
            const int row = row0 + mi * 16 + rr * 8;
            #pragma unroll
            for (int j = 0; j < 2 * NJ; ++j) {
                float v0 = c[mi][j][rr * 2], v1 = c[mi][j][rr * 2 + 1];
                if (RELU2) {
                    v0 = fmaxf(v0, 0.0f); v0 *= v0;
                    v1 = fmaxf(v1, 0.0f); v1 *= v1;
                }
                if (OUT16) {
                    __half* base = (__half*)Cv + (size_t)row * ldc + col0;
                    __half2 hv = __floats2half2_rn(v0, v1);
                    *reinterpret_cast<__half2*>(base + j * 8) = hv;
                } else {
                    float* base = (float*)Cv + (size_t)row * ldc + col0;
                    *reinterpret_cast<float2*>(base + j * 8) = make_float2(v0, v1);
                }
            }
        }
}

// signal: all threads fence, sync, then one thread bumps the band counters
__device__ __forceinline__ void signal_bands(int band0, int nbands)
{
    __threadfence();
    __syncthreads();
    if (threadIdx.x == 0) {
        atomicAdd(&g_cnt[band0], 1);
        if (nbands == 2) atomicAdd(&g_cnt[band0 + 1], 1);
    }
}

// wait: thread 0 spins until each band has all 32 n-tiles of h complete
__device__ __forceinline__ void wait_bands(int band0, int nbands)
{
    if (threadIdx.x == 0) {
        while (atomicAdd(&g_cnt[band0], 0) < 32) { __nanosleep(64); }
        if (nbands == 2)
            while (atomicAdd(&g_cnt[band0 + 1], 0) < 32) { __nanosleep(64); }
        __threadfence();
    }
    __syncthreads();
}

// fused GEMM1 + GEMM2: bids [0,2336) = GEMM1 tiles, [2336,3064) = GEMM2 tiles.
// GEMM2 tiles wait on per-64-row-band counters of h (filled by GEMM1 tiles).
__global__ void __launch_bounds__(256, 2) gemm12_fused(
    const __half* __restrict__ xh, const __half* __restrict__ wfc,
    __half* __restrict__ h, const __half* __restrict__ wpr,
    float* __restrict__ out)
{
    const int bx = blockIdx.x;
    if (bx < G1_TOTAL) {
        if (bx < G1_BIG_TILES) {
            const int m0 = (bx >> 5) * 128;
            gemm_body<true, true, 128, 4>(xh, wfc, h, D_DIM, H_DIM, m0, (bx & 31) * 128);
            signal_bands(m0 >> 6, 2);
        } else {
            const int i = bx - G1_BIG_TILES;
            const int m0 = G1_SMALL_ROW0 + (i >> 5) * 64;
            gemm_body<true, true, 64, 2>(xh, wfc, h, D_DIM, H_DIM, m0, (i & 31) * 128);
            signal_bands(m0 >> 6, 1);
        }
    } else {
        const int i = bx - G1_TOTAL;
        if (i < G2_BIG_TILES) {
            const int m0 = (i >> 3) * 128;
            wait_bands(m0 >> 6, 2);
            gemm_body<false, false, 128, 4>(h, wpr, out, H_DIM, D_DIM, m0, (i & 7) * 128);
        } else {
            const int j = i - G2_BIG_TILES;
            const int m0 = G2_SMALL_ROW0 + (j >> 3) * 64;
            wait_bands(m0 >> 6, 1);
            gemm_body<false, false, 64, 2>(h, wpr, out, H_DIM, D_DIM, m0, (j & 7) * 128);
        }
    }
}

// ---------------- fused fp32 -> fp16 RN pre-pass + counter reset ----------------
// blocks [0,1184): x (2M float4); [1184,1776): wfc (1M); [1776,2368): wpr (1M)
__global__ void to_half_all_kernel(const float4* __restrict__ x,   __half2* __restrict__ xo,
                                   const float4* __restrict__ wf,  __half2* __restrict__ wfo,
                                   const float4* __restrict__ wp,  __half2* __restrict__ wpo)
{
    if (blockIdx.x == 0 && threadIdx.x < 128) g_cnt[threadIdx.x] = 0;  // reset band counters
    const float4* src; __half2* dst; int n4, b0, nb;
    if (blockIdx.x < 1184)      { src = x;  dst = xo;  n4 = T_DIM * D_DIM / 4; b0 = 0;    nb = 1184; }
    else if (blockIdx.x < 1776) { src = wf; dst = wfo; n4 = H_DIM * D_DIM / 4; b0 = 1184; nb = 592; }
    else                        { src = wp; dst = wpo; n4 = D_DIM * H_DIM / 4; b0 = 1776; nb = 592; }
    const int stride = nb * 256;
    #pragma unroll 2
    for (int i = (blockIdx.x - b0) * 256 + threadIdx.x; i < n4; i += stride) {
        float4 v = src[i];
        dst[2 * i]     = __floats2half2_rn(v.x, v.y);
        dst[2 * i + 1] = __floats2half2_rn(v.z, v.w);
    }
}

// ---------------- host side ----------------
extern "C" void kernel_launch(void* const* d_in, const int* in_sizes, int n_in,
                              void* d_out, int out_size)
{
    const float* x   = (const float*)d_in[0];  // [8192, 1024]
    const float* wfc = (const float*)d_in[1];  // [4096, 1024]
    const float* wpr = (const float*)d_in[2];  // [1024, 4096]
    float* out = (float*)d_out;                // [8192, 1024]

    __half *h, *xh, *wfch, *wprh;
    cudaGetSymbolAddress((void**)&h,    g_h);
    cudaGetSymbolAddress((void**)&xh,   g_xh);
    cudaGetSymbolAddress((void**)&wfch, g_wfc);
    cudaGetSymbolAddress((void**)&wprh, g_wpr);

    cudaFuncSetAttribute(gemm12_fused,
                         cudaFuncAttributeMaxDynamicSharedMemorySize, SMEM_TOTAL);

    // pre-pass: fp32 -> fp16 (RN) conversion + band-counter reset (strictly precedes fused GEMM)
    to_half_all_kernel<<<2368, 256>>>((const float4*)x,   (__half2*)xh,
                                      (const float4*)wfc, (__half2*)wfch,
                                      (const float4*)wpr, (__half2*)wprh);

    // fused GEMM1 (h = relu(x Wfc^T)^2) + GEMM2 (out = h Wpr^T) with band-dependency overlap
    gemm12_fused<<<G1_TOTAL + G2_TOTAL, 256, SMEM_TOTAL>>>(xh, wfch, h, wprh, out);
}